// round 7
// baseline (speedup 1.0000x reference)
#include <cuda_runtime.h>
#include <cstdint>

// Problem constants
#define NIMG 256          // B*L
#define CCH  64           // channels
#define HW   32           // height = width
#define IMGSZ (CCH*HW*HW) // 65536 floats per image
#define NODES 256

// Scratch (device globals). Paired layout for conv inputs:
// float2 array [n][cc8][q4][1024]: elem = (v[ch=8cc+q], v[ch=8cc+q+4]), tf32-rounded
__device__ float2 g_xp[NIMG * IMGSZ / 2];  // pairified+rounded x
__device__ float2 g_xs[NIMG * IMGSZ / 2];  // aggregated x (paired, rounded)
__device__ float2 g_h [NIMG * IMGSZ / 2];  // hidden (paired, rounded)
__device__ float2 g_hs[NIMG * IMGSZ / 2];  // aggregated hidden (paired, rounded)
__device__ int   g_nbr[NODES * 8];
__device__ int   g_cnt[NODES];
__device__ int   g_mode;

// Pre-transformed weights, tf32 bits:
// [chunk32 = layer*16 + half*8 + cc][tap9][qid8][q4][nt pad 10] uint2
#define W_CHUNK  2880                  // uint2 per chunk
#define W_TAP_U4 160                   // uint4 per tap block
#define WPREP_TOTAL (32 * W_CHUNK)
__device__ uint2 g_wprep[WPREP_TOTAL];

// paired patch layout (uint2 elems): [q4][row10][col36], q-stride 372
// q*372: mod-16 spread => q*4+qid distinct per half-warp phase (LDS.64 clean)
#define P2_QSTR 372
#define P2_RSTR 36
#define P2_ELEMS 1488   // 4*372 uint2 per buffer
#define SMEM_BYTES (2*P2_ELEMS*8 + 2*W_CHUNK*8)   // 23808 + 46080 = 69888

__device__ __forceinline__ uint32_t f2tf32(float f) {
    uint32_t u;
    asm("cvt.rna.tf32.f32 %0, %1;" : "=r"(u) : "f"(f));
    return u;
}

__device__ __forceinline__ void cp16(void* s, const void* g) {
    uint32_t sa = (uint32_t)__cvta_generic_to_shared(s);
    asm volatile("cp.async.cg.shared.global [%0], [%1], 16;" :: "r"(sa), "l"(g));
}

__device__ __forceinline__ void cp8(void* s, const void* g) {
    uint32_t sa = (uint32_t)__cvta_generic_to_shared(s);
    asm volatile("cp.async.ca.shared.global [%0], [%1], 8;" :: "r"(sa), "l"(g));
}

__device__ __forceinline__ void mma_tf32(float& d0, float& d1, float& d2, float& d3,
                                         uint32_t a0, uint32_t a1, uint32_t a2, uint32_t a3,
                                         uint32_t b0, uint32_t b1) {
    asm volatile(
        "mma.sync.aligned.m16n8k8.row.col.f32.tf32.tf32.f32 "
        "{%0,%1,%2,%3},{%4,%5,%6,%7},{%8,%9},{%0,%1,%2,%3};"
        : "+f"(d0), "+f"(d1), "+f"(d2), "+f"(d3)
        : "r"(a0), "r"(a1), "r"(a2), "r"(a3), "r"(b0), "r"(b1));
}

// ---------------------------------------------------------------------------
// Mask dtype detection + neighbor list build (unchanged, correct)
// ---------------------------------------------------------------------------
__global__ void detect_kernel(const void* m) {
    __shared__ int bad;
    int row = threadIdx.x;
    if (row == 0) bad = 0;
    __syncthreads();
    {
        const unsigned char* p = (const unsigned char*)m + row * 64;
        int c = 0;
        for (int j = 0; j < 64; j++) c += (p[j] != 0);
        if (c != 4) atomicOr(&bad, 1);
    }
    __syncthreads();
    int ok8 = !bad;
    __syncthreads();
    if (row == 0) bad = 0;
    __syncthreads();
    if (!ok8) {
        const unsigned short* p = (const unsigned short*)m + row * 64;
        int c = 0;
        for (int j = 0; j < 64; j++) c += (p[j] != 0);
        if (c != 4) atomicOr(&bad, 1);
    }
    __syncthreads();
    int ok16 = (!ok8) && (!bad);
    if (row == 0) g_mode = ok8 ? 0 : (ok16 ? 1 : 2);
}

__global__ void build_kernel(const void* m) {
    int row = threadIdx.x;
    if (row >= NODES) return;
    int mode = g_mode;
    int base = (row >> 6) << 6;
    int cnt = 0;
    if (mode == 0) {
        const unsigned char* p = (const unsigned char*)m + row * 64;
        for (int j = 0; j < 64; j++)
            if (p[j]) { if (cnt < 8) g_nbr[row * 8 + cnt] = base + j; cnt++; }
    } else if (mode == 1) {
        const unsigned short* p = (const unsigned short*)m + row * 64;
        for (int j = 0; j < 64; j++)
            if (p[j]) { if (cnt < 8) g_nbr[row * 8 + cnt] = base + j; cnt++; }
    } else {
        const unsigned int* p = (const unsigned int*)m + row * 64;
        for (int j = 0; j < 64; j++)
            if (p[j]) { if (cnt < 8) g_nbr[row * 8 + cnt] = base + j; cnt++; }
    }
    g_cnt[row] = cnt;
}

// ---------------------------------------------------------------------------
// Weight pre-transform (unchanged layout; pairs (ci=cb+q, ci=cb+q+4))
// ---------------------------------------------------------------------------
__global__ void prep_weights(const float* __restrict__ w_x0, const float* __restrict__ w_n0,
                             const float* __restrict__ w_x1, const float* __restrict__ w_n1) {
    int e = blockIdx.x * 256 + threadIdx.x;
    if (e >= WPREP_TOTAL) return;
    int nt = e % 10; int t = e / 10;
    int q   = t & 3;  t >>= 2;
    int qid = t & 7;  t >>= 3;
    int tap = t % 9;  t /= 9;
    int cc   = t & 7;
    int half = (t >> 3) & 1;
    int layer = t >> 4;
    const float* w = layer ? (half ? w_n1 : w_x1) : (half ? w_n0 : w_x0);
    uint2 v = make_uint2(0u, 0u);
    if (nt < 8) {
        int co = nt * 8 + qid;
        int cb = cc * 8;
        v.x = f2tf32(w[co * 576 + (cb + q) * 9 + tap]);
        v.y = f2tf32(w[co * 576 + (cb + q + 4) * 9 + tap]);
    }
    g_wprep[e] = v;
}

// ---------------------------------------------------------------------------
// Pairify + tf32-round x into paired layout
// ---------------------------------------------------------------------------
__global__ void pairify_kernel(const float* __restrict__ x, float2* __restrict__ xp) {
    int e = blockIdx.x * 256 + threadIdx.x;   // float2 element index
    // e = ((n*8 + cc)*4 + q)*1024 + p
    int p  = e & 1023;
    int q  = (e >> 10) & 3;
    int cc = (e >> 12) & 7;
    int n  = e >> 15;
    int ch = (n * CCH + cc * 8 + q) * 1024 + p;
    float2 v;
    v.x = __uint_as_float(f2tf32(x[ch]));
    v.y = __uint_as_float(f2tf32(x[ch + 4096]));   // ch+4 channels = +4*1024
    xp[e] = v;
}

// ---------------------------------------------------------------------------
// Neighbor aggregation on paired arrays (elementwise); rounds output
// ---------------------------------------------------------------------------
__global__ void agg_kernel(const float* __restrict__ src, float* __restrict__ dst) {
    int node = blockIdx.x;
    int cnt = g_cnt[node];
    if (cnt > 8) cnt = 8;
    int i0 = blockIdx.y * blockDim.x + threadIdx.x;
    int stride = gridDim.y * blockDim.x;
    const float4* s4 = (const float4*)src;
    float4* d4 = (float4*)dst;
    int nb[8];
    for (int k = 0; k < cnt; k++) nb[k] = g_nbr[node * 8 + k];
    const int n4 = IMGSZ / 4;
    for (int i = i0; i < n4; i += stride) {
        float4 acc = make_float4(0.f, 0.f, 0.f, 0.f);
        for (int k = 0; k < cnt; k++) {
            float4 v = s4[nb[k] * n4 + i];
            acc.x += v.x; acc.y += v.y; acc.z += v.z; acc.w += v.w;
        }
        acc.x = __uint_as_float(f2tf32(acc.x));
        acc.y = __uint_as_float(f2tf32(acc.y));
        acc.z = __uint_as_float(f2tf32(acc.z));
        acc.w = __uint_as_float(f2tf32(acc.w));
        d4[node * n4 + i] = acc;
    }
}

// ---------------------------------------------------------------------------
// Conv: paired patch (LDS.64 A-frags), cp.async fill, 2-stage pipeline
// ---------------------------------------------------------------------------
__device__ __forceinline__ void issue_chunk(uint2* pp, uint4* wdst,
                                            const uint2* __restrict__ wsrc,
                                            const float2* __restrict__ img,  // +(n*8+cc)*4*1024
                                            int y0, int tid) {
    const uint4* ws = (const uint4*)wsrc;
#pragma unroll
    for (int k = 0; k < 6; k++) {
        int idx = tid + k * 256;
        if (idx < W_CHUNK / 2) cp16(wdst + idx, ws + idx);
    }
    // paired patch: 4 q-slots x 10 rows x 32 cols of float2
#pragma unroll
    for (int k = 0; k < 5; k++) {
        int i = tid + k * 256;          // < 1280
        int col = i & 31;
        int r = (i >> 5) % 10;
        int qs = i / 320;
        int gy = y0 + r - 1;
        if (gy >= 0 && gy < HW)
            cp8(pp + qs * P2_QSTR + r * P2_RSTR + 1 + col,
                img + qs * 1024 + gy * 32 + col);
    }
    asm volatile("cp.async.commit_group;" ::: "memory");
}

__device__ __forceinline__ void compute_chunk(const uint2* __restrict__ pp,
                                              const uint4* __restrict__ wq,
                                              int w, int qid, int q, int wtbase,
                                              float (&acc)[2][8][4]) {
    uint4 bb[2][4];
#pragma unroll
    for (int j = 0; j < 4; j++) bb[0][j] = wq[wtbase + j];

#pragma unroll
    for (int tap = 0; tap < 9; tap++) {
        const int ty = tap / 3, tx = tap % 3;
        const int cur = tap & 1;
        if (tap < 8) {
            const uint4* wn = wq + (tap + 1) * W_TAP_U4 + wtbase;
#pragma unroll
            for (int j = 0; j < 4; j++) bb[1 - cur][j] = wn[j];
        }
        // A fragments: 4 LDS.64 per tap; pair = (ch q, ch q+4)
        const int base = q * P2_QSTR + (w + ty) * P2_RSTR + qid + tx;
        uint2 va0 = pp[base];        // (a0, a2) mt0
        uint2 vb0 = pp[base + 8];    // (a1, a3) mt0
        uint2 va1 = pp[base + 16];   // (a0, a2) mt1
        uint2 vb1 = pp[base + 24];   // (a1, a3) mt1
        const uint32_t* b = (const uint32_t*)bb[cur];
#pragma unroll
        for (int nt = 0; nt < 8; nt++)
            mma_tf32(acc[0][nt][0], acc[0][nt][1], acc[0][nt][2], acc[0][nt][3],
                     va0.x, vb0.x, va0.y, vb0.y, b[2 * nt], b[2 * nt + 1]);
#pragma unroll
        for (int nt = 0; nt < 8; nt++)
            mma_tf32(acc[1][nt][0], acc[1][nt][1], acc[1][nt][2], acc[1][nt][3],
                     va1.x, vb1.x, va1.y, vb1.y, b[2 * nt], b[2 * nt + 1]);
    }
}

// EPI 0: standard fp32 out + residual; EPI 1: paired+rounded out (no resid)
template <int EPI>
__global__ __launch_bounds__(256, 2)
void conv_kernel(const float2* __restrict__ inA, const float2* __restrict__ inB,
                 const uint2* __restrict__ wprep,
                 const float* __restrict__ bA,  const float* __restrict__ bB,
                 const float* __restrict__ resid, float* __restrict__ out) {
    extern __shared__ uint8_t smem[];
    uint2* ppB[2];
    ppB[0] = (uint2*)smem;
    ppB[1] = ppB[0] + P2_ELEMS;
    uint4* wsmB[2];
    wsmB[0] = (uint4*)(ppB[1] + P2_ELEMS);
    wsmB[1] = wsmB[0] + W_CHUNK / 2;

    const int n = blockIdx.y;
    const int rb = blockIdx.x;
    const int tid = threadIdx.x;
    const int w = tid >> 5;
    const int lane = tid & 31;
    const int qid = lane >> 2;
    const int q = lane & 3;
    const int y0 = rb * 8;

    // zero both patch buffers once (halo stays zero)
#pragma unroll
    for (int k = 0; k < 12; k++) {
        int i = tid + k * 256;
        if (i < 2 * P2_ELEMS) ppB[0][i] = make_uint2(0u, 0u);
    }
    __syncthreads();

    float acc[2][8][4];
#pragma unroll
    for (int mt = 0; mt < 2; mt++)
#pragma unroll
        for (int nt = 0; nt < 8; nt++)
#pragma unroll
            for (int r = 0; r < 4; r++) acc[mt][nt][r] = 0.f;

    // prolog: chunk 0
    issue_chunk(ppB[0], wsmB[0], wprep, inA + n * 32768, y0, tid);
    asm volatile("cp.async.wait_group 0;" ::: "memory");
    __syncthreads();

    const int wtbase = (qid * 4 + q) * 5;

    for (int it = 0; it < 16; ++it) {
        const int p = it & 1;
        if (it < 15) {
            const int jt = it + 1;
            const float2* img = ((jt >> 3) ? inB : inA) + (n * 8 + (jt & 7)) * 4096;
            issue_chunk(ppB[1 - p], wsmB[1 - p], wprep + jt * W_CHUNK, img, y0, tid);
        }
        compute_chunk(ppB[p], wsmB[p], w, qid, q, wtbase, acc);
        asm volatile("cp.async.wait_group 0;" ::: "memory");
        __syncthreads();
    }

    // epilogue
    const int gy = y0 + w;
    const float cntf = (float)g_cnt[n];
#pragma unroll
    for (int nt = 0; nt < 8; nt++) {
        const int co = nt * 8 + 2 * q;
        const float bias0 = bA[co]     + cntf * bB[co];
        const float bias1 = bA[co + 1] + cntf * bB[co + 1];
#pragma unroll
        for (int mt = 0; mt < 2; mt++) {
            const int xa = mt * 16 + qid;
            const int xc = xa + 8;
            float r0 = acc[mt][nt][0] + bias0;   // (xa, co)
            float r1 = acc[mt][nt][1] + bias1;   // (xa, co+1)
            float r2 = acc[mt][nt][2] + bias0;   // (xc, co)
            float r3 = acc[mt][nt][3] + bias1;   // (xc, co+1)
            if (EPI == 0) {
                const int o0 = ((n * CCH + co) * HW + gy) * HW;
                r0 += resid[o0 + xa];
                r1 += resid[o0 + 1024 + xa];
                r2 += resid[o0 + xc];
                r3 += resid[o0 + 1024 + xc];
                out[o0 + xa]        = fmaxf(r0, 0.f);
                out[o0 + 1024 + xa] = fmaxf(r1, 0.f);
                out[o0 + xc]        = fmaxf(r2, 0.f);
                out[o0 + 1024 + xc] = fmaxf(r3, 0.f);
            } else {
                // paired store: co -> (cc=co>>3, slot=co&3, comp=(co>>2)&1)
                r0 = __uint_as_float(f2tf32(fmaxf(r0, 0.f)));
                r1 = __uint_as_float(f2tf32(fmaxf(r1, 0.f)));
                r2 = __uint_as_float(f2tf32(fmaxf(r2, 0.f)));
                r3 = __uint_as_float(f2tf32(fmaxf(r3, 0.f)));
                const int co1 = co + 1;
                const int b0 = ((((n * 8 + nt) * 4 + (co  & 3)) * 1024) + gy * 32) * 2 + ((co  >> 2) & 1);
                const int b1 = ((((n * 8 + nt) * 4 + (co1 & 3)) * 1024) + gy * 32) * 2 + ((co1 >> 2) & 1);
                out[b0 + 2 * xa] = r0;
                out[b1 + 2 * xa] = r1;
                out[b0 + 2 * xc] = r2;
                out[b1 + 2 * xc] = r3;
            }
        }
    }
}

// ---------------------------------------------------------------------------
extern "C" void kernel_launch(void* const* d_in, const int* in_sizes, int n_in,
                              void* d_out, int out_size) {
    const float* x    = (const float*)d_in[0];
    const float* w_x0 = (const float*)d_in[1];
    const float* b_x0 = (const float*)d_in[2];
    const float* w_n0 = (const float*)d_in[3];
    const float* b_n0 = (const float*)d_in[4];
    const float* w_x1 = (const float*)d_in[5];
    const float* b_x1 = (const float*)d_in[6];
    const float* w_n1 = (const float*)d_in[7];
    const float* b_n1 = (const float*)d_in[8];
    const void*  msk  = d_in[9];
    float* out = (float*)d_out;

    float2 *xp, *xs, *h, *hs;
    uint2* wprep;
    cudaGetSymbolAddress((void**)&xp, g_xp);
    cudaGetSymbolAddress((void**)&xs, g_xs);
    cudaGetSymbolAddress((void**)&h,  g_h);
    cudaGetSymbolAddress((void**)&hs, g_hs);
    cudaGetSymbolAddress((void**)&wprep, g_wprep);

    static bool attr_set = false;
    if (!attr_set) {
        cudaFuncSetAttribute(conv_kernel<0>, cudaFuncAttributeMaxDynamicSharedMemorySize,
                             SMEM_BYTES);
        cudaFuncSetAttribute(conv_kernel<1>, cudaFuncAttributeMaxDynamicSharedMemorySize,
                             SMEM_BYTES);
        attr_set = true;
    }

    detect_kernel<<<1, 256>>>(msk);
    build_kernel<<<1, 256>>>(msk);
    prep_weights<<<(WPREP_TOTAL + 255) / 256, 256>>>(w_x0, w_n0, w_x1, w_n1);
    pairify_kernel<<<NIMG * IMGSZ / 2 / 256, 256>>>(x, xp);

    dim3 agrid(NODES, 16);
    dim3 cgrid(4, NIMG);

    // layer 1: xs = agg(xp); h = relu(conv) stored paired+rounded
    agg_kernel<<<agrid, 256>>>((const float*)xp, (float*)xs);
    conv_kernel<1><<<cgrid, 256, SMEM_BYTES>>>(xp, xs, wprep, b_x0, b_n0,
                                               nullptr, (float*)h);

    // layer 2: hs = agg(h); out = relu(conv + x) standard fp32
    agg_kernel<<<agrid, 256>>>((const float*)h, (float*)hs);
    conv_kernel<0><<<cgrid, 256, SMEM_BYTES>>>(h, hs, wprep + 16 * W_CHUNK, b_x1, b_n1,
                                               x, out);
}

// round 8
// speedup vs baseline: 1.0053x; 1.0053x over previous
#include <cuda_runtime.h>
#include <cstdint>

// Problem constants
#define NIMG 256          // B*L
#define CCH  64           // channels
#define HW   32           // height = width
#define IMGSZ (CCH*HW*HW) // 65536 floats per image
#define NODES 256

// Scratch (device globals). Paired layout for conv inputs:
// float2 array [n][cc8][q4][1024]: elem = (v[ch=8cc+q], v[ch=8cc+q+4]), tf32-rounded
__device__ float2 g_xp[NIMG * IMGSZ / 2];  // pairified+rounded x
__device__ float2 g_xs[NIMG * IMGSZ / 2];  // aggregated x (paired, rounded)
__device__ float2 g_h [NIMG * IMGSZ / 2];  // hidden (paired, rounded)
__device__ float2 g_hs[NIMG * IMGSZ / 2];  // aggregated hidden (paired, rounded)
__device__ int   g_nbr[NODES * 8];
__device__ int   g_cnt[NODES];
__device__ int   g_mode;

// Pre-transformed weights, tf32 bits:
// [chunk32 = layer*16 + half*8 + cc][tap9][qid8][q4][nt pad 10] uint2
#define W_CHUNK  2880                  // uint2 per chunk
#define W_TAP_U4 160                   // uint4 per tap block
#define WPREP_TOTAL (32 * W_CHUNK)
__device__ uint2 g_wprep[WPREP_TOTAL];

// paired patch layout (uint2 elems): [q4][row10][col36], q-stride 372
// q*372: mod-16 spread => q*4+qid distinct per half-warp phase (LDS.64 clean)
#define P2_QSTR 372
#define P2_RSTR 36
#define P2_ELEMS 1488   // 4*372 uint2 per buffer
#define SMEM_BYTES (2*P2_ELEMS*8 + 2*W_CHUNK*8)   // 23808 + 46080 = 69888

__device__ __forceinline__ uint32_t f2tf32(float f) {
    uint32_t u;
    asm("cvt.rna.tf32.f32 %0, %1;" : "=r"(u) : "f"(f));
    return u;
}

__device__ __forceinline__ void cp16(void* s, const void* g) {
    uint32_t sa = (uint32_t)__cvta_generic_to_shared(s);
    asm volatile("cp.async.cg.shared.global [%0], [%1], 16;" :: "r"(sa), "l"(g));
}

__device__ __forceinline__ void cp8(void* s, const void* g) {
    uint32_t sa = (uint32_t)__cvta_generic_to_shared(s);
    asm volatile("cp.async.ca.shared.global [%0], [%1], 8;" :: "r"(sa), "l"(g));
}

__device__ __forceinline__ void mma_tf32(float& d0, float& d1, float& d2, float& d3,
                                         uint32_t a0, uint32_t a1, uint32_t a2, uint32_t a3,
                                         uint32_t b0, uint32_t b1) {
    asm volatile(
        "mma.sync.aligned.m16n8k8.row.col.f32.tf32.tf32.f32 "
        "{%0,%1,%2,%3},{%4,%5,%6,%7},{%8,%9},{%0,%1,%2,%3};"
        : "+f"(d0), "+f"(d1), "+f"(d2), "+f"(d3)
        : "r"(a0), "r"(a1), "r"(a2), "r"(a3), "r"(b0), "r"(b1));
}

// ---------------------------------------------------------------------------
// Mask dtype detection + neighbor list build (unchanged, correct)
// ---------------------------------------------------------------------------
__global__ void detect_kernel(const void* m) {
    __shared__ int bad;
    int row = threadIdx.x;
    if (row == 0) bad = 0;
    __syncthreads();
    {
        const unsigned char* p = (const unsigned char*)m + row * 64;
        int c = 0;
        for (int j = 0; j < 64; j++) c += (p[j] != 0);
        if (c != 4) atomicOr(&bad, 1);
    }
    __syncthreads();
    int ok8 = !bad;
    __syncthreads();
    if (row == 0) bad = 0;
    __syncthreads();
    if (!ok8) {
        const unsigned short* p = (const unsigned short*)m + row * 64;
        int c = 0;
        for (int j = 0; j < 64; j++) c += (p[j] != 0);
        if (c != 4) atomicOr(&bad, 1);
    }
    __syncthreads();
    int ok16 = (!ok8) && (!bad);
    if (row == 0) g_mode = ok8 ? 0 : (ok16 ? 1 : 2);
}

__global__ void build_kernel(const void* m) {
    int row = threadIdx.x;
    if (row >= NODES) return;
    int mode = g_mode;
    int base = (row >> 6) << 6;
    int cnt = 0;
    if (mode == 0) {
        const unsigned char* p = (const unsigned char*)m + row * 64;
        for (int j = 0; j < 64; j++)
            if (p[j]) { if (cnt < 8) g_nbr[row * 8 + cnt] = base + j; cnt++; }
    } else if (mode == 1) {
        const unsigned short* p = (const unsigned short*)m + row * 64;
        for (int j = 0; j < 64; j++)
            if (p[j]) { if (cnt < 8) g_nbr[row * 8 + cnt] = base + j; cnt++; }
    } else {
        const unsigned int* p = (const unsigned int*)m + row * 64;
        for (int j = 0; j < 64; j++)
            if (p[j]) { if (cnt < 8) g_nbr[row * 8 + cnt] = base + j; cnt++; }
    }
    g_cnt[row] = cnt;
}

// ---------------------------------------------------------------------------
// Weight pre-transform (unchanged layout; pairs (ci=cb+q, ci=cb+q+4))
// ---------------------------------------------------------------------------
__global__ void prep_weights(const float* __restrict__ w_x0, const float* __restrict__ w_n0,
                             const float* __restrict__ w_x1, const float* __restrict__ w_n1) {
    int e = blockIdx.x * 256 + threadIdx.x;
    if (e >= WPREP_TOTAL) return;
    int nt = e % 10; int t = e / 10;
    int q   = t & 3;  t >>= 2;
    int qid = t & 7;  t >>= 3;
    int tap = t % 9;  t /= 9;
    int cc   = t & 7;
    int half = (t >> 3) & 1;
    int layer = t >> 4;
    const float* w = layer ? (half ? w_n1 : w_x1) : (half ? w_n0 : w_x0);
    uint2 v = make_uint2(0u, 0u);
    if (nt < 8) {
        int co = nt * 8 + qid;
        int cb = cc * 8;
        v.x = f2tf32(w[co * 576 + (cb + q) * 9 + tap]);
        v.y = f2tf32(w[co * 576 + (cb + q + 4) * 9 + tap]);
    }
    g_wprep[e] = v;
}

// ---------------------------------------------------------------------------
// Pairify + tf32-round x into paired layout
// ---------------------------------------------------------------------------
__global__ void pairify_kernel(const float* __restrict__ x, float2* __restrict__ xp) {
    int e = blockIdx.x * 256 + threadIdx.x;   // float2 element index
    // e = ((n*8 + cc)*4 + q)*1024 + p
    int p  = e & 1023;
    int q  = (e >> 10) & 3;
    int cc = (e >> 12) & 7;
    int n  = e >> 15;
    int ch = (n * CCH + cc * 8 + q) * 1024 + p;
    float2 v;
    v.x = __uint_as_float(f2tf32(x[ch]));
    v.y = __uint_as_float(f2tf32(x[ch + 4096]));   // ch+4 channels = +4*1024
    xp[e] = v;
}

// ---------------------------------------------------------------------------
// Neighbor aggregation on paired arrays (elementwise); rounds output
// ---------------------------------------------------------------------------
__global__ void agg_kernel(const float* __restrict__ src, float* __restrict__ dst) {
    int node = blockIdx.x;
    int cnt = g_cnt[node];
    if (cnt > 8) cnt = 8;
    int i0 = blockIdx.y * blockDim.x + threadIdx.x;
    int stride = gridDim.y * blockDim.x;
    const float4* s4 = (const float4*)src;
    float4* d4 = (float4*)dst;
    int nb[8];
    for (int k = 0; k < cnt; k++) nb[k] = g_nbr[node * 8 + k];
    const int n4 = IMGSZ / 4;
    for (int i = i0; i < n4; i += stride) {
        float4 acc = make_float4(0.f, 0.f, 0.f, 0.f);
        for (int k = 0; k < cnt; k++) {
            float4 v = s4[nb[k] * n4 + i];
            acc.x += v.x; acc.y += v.y; acc.z += v.z; acc.w += v.w;
        }
        acc.x = __uint_as_float(f2tf32(acc.x));
        acc.y = __uint_as_float(f2tf32(acc.y));
        acc.z = __uint_as_float(f2tf32(acc.z));
        acc.w = __uint_as_float(f2tf32(acc.w));
        d4[node * n4 + i] = acc;
    }
}

// ---------------------------------------------------------------------------
// Conv: paired patch (LDS.64 A-frags), cp.async fill, 2-stage pipeline
// ---------------------------------------------------------------------------
__device__ __forceinline__ void issue_chunk(uint2* pp, uint4* wdst,
                                            const uint2* __restrict__ wsrc,
                                            const float2* __restrict__ img,  // +(n*8+cc)*4*1024
                                            int y0, int tid) {
    const uint4* ws = (const uint4*)wsrc;
#pragma unroll
    for (int k = 0; k < 6; k++) {
        int idx = tid + k * 256;
        if (idx < W_CHUNK / 2) cp16(wdst + idx, ws + idx);
    }
    // paired patch: 4 q-slots x 10 rows x 32 cols of float2
#pragma unroll
    for (int k = 0; k < 5; k++) {
        int i = tid + k * 256;          // < 1280
        int col = i & 31;
        int r = (i >> 5) % 10;
        int qs = i / 320;
        int gy = y0 + r - 1;
        if (gy >= 0 && gy < HW)
            cp8(pp + qs * P2_QSTR + r * P2_RSTR + 1 + col,
                img + qs * 1024 + gy * 32 + col);
    }
    asm volatile("cp.async.commit_group;" ::: "memory");
}

__device__ __forceinline__ void compute_chunk(const uint2* __restrict__ pp,
                                              const uint4* __restrict__ wq,
                                              int w, int qid, int q, int wtbase,
                                              float (&acc)[2][8][4]) {
    uint4 bb[2][4];
#pragma unroll
    for (int j = 0; j < 4; j++) bb[0][j] = wq[wtbase + j];

#pragma unroll
    for (int tap = 0; tap < 9; tap++) {
        const int ty = tap / 3, tx = tap % 3;
        const int cur = tap & 1;
        if (tap < 8) {
            const uint4* wn = wq + (tap + 1) * W_TAP_U4 + wtbase;
#pragma unroll
            for (int j = 0; j < 4; j++) bb[1 - cur][j] = wn[j];
        }
        // A fragments: 4 LDS.64 per tap; pair = (ch q, ch q+4)
        const int base = q * P2_QSTR + (w + ty) * P2_RSTR + qid + tx;
        uint2 va0 = pp[base];        // (a0, a2) mt0
        uint2 vb0 = pp[base + 8];    // (a1, a3) mt0
        uint2 va1 = pp[base + 16];   // (a0, a2) mt1
        uint2 vb1 = pp[base + 24];   // (a1, a3) mt1
        const uint32_t* b = (const uint32_t*)bb[cur];
#pragma unroll
        for (int nt = 0; nt < 8; nt++)
            mma_tf32(acc[0][nt][0], acc[0][nt][1], acc[0][nt][2], acc[0][nt][3],
                     va0.x, vb0.x, va0.y, vb0.y, b[2 * nt], b[2 * nt + 1]);
#pragma unroll
        for (int nt = 0; nt < 8; nt++)
            mma_tf32(acc[1][nt][0], acc[1][nt][1], acc[1][nt][2], acc[1][nt][3],
                     va1.x, vb1.x, va1.y, vb1.y, b[2 * nt], b[2 * nt + 1]);
    }
}

// EPI 0: standard fp32 out + residual; EPI 1: paired+rounded out (no resid)
template <int EPI>
__global__ __launch_bounds__(256, 2)
void conv_kernel(const float2* __restrict__ inA, const float2* __restrict__ inB,
                 const uint2* __restrict__ wprep,
                 const float* __restrict__ bA,  const float* __restrict__ bB,
                 const float* __restrict__ resid, float* __restrict__ out) {
    extern __shared__ uint8_t smem[];
    uint2* ppB[2];
    ppB[0] = (uint2*)smem;
    ppB[1] = ppB[0] + P2_ELEMS;
    uint4* wsmB[2];
    wsmB[0] = (uint4*)(ppB[1] + P2_ELEMS);
    wsmB[1] = wsmB[0] + W_CHUNK / 2;

    const int n = blockIdx.y;
    const int rb = blockIdx.x;
    const int tid = threadIdx.x;
    const int w = tid >> 5;
    const int lane = tid & 31;
    const int qid = lane >> 2;
    const int q = lane & 3;
    const int y0 = rb * 8;

    // zero both patch buffers once (halo stays zero)
#pragma unroll
    for (int k = 0; k < 12; k++) {
        int i = tid + k * 256;
        if (i < 2 * P2_ELEMS) ppB[0][i] = make_uint2(0u, 0u);
    }
    __syncthreads();

    float acc[2][8][4];
#pragma unroll
    for (int mt = 0; mt < 2; mt++)
#pragma unroll
        for (int nt = 0; nt < 8; nt++)
#pragma unroll
            for (int r = 0; r < 4; r++) acc[mt][nt][r] = 0.f;

    // prolog: chunk 0
    issue_chunk(ppB[0], wsmB[0], wprep, inA + n * 32768, y0, tid);
    asm volatile("cp.async.wait_group 0;" ::: "memory");
    __syncthreads();

    const int wtbase = (qid * 4 + q) * 5;

    for (int it = 0; it < 16; ++it) {
        const int p = it & 1;
        if (it < 15) {
            const int jt = it + 1;
            const float2* img = ((jt >> 3) ? inB : inA) + (n * 8 + (jt & 7)) * 4096;
            issue_chunk(ppB[1 - p], wsmB[1 - p], wprep + jt * W_CHUNK, img, y0, tid);
        }
        compute_chunk(ppB[p], wsmB[p], w, qid, q, wtbase, acc);
        asm volatile("cp.async.wait_group 0;" ::: "memory");
        __syncthreads();
    }

    // epilogue
    const int gy = y0 + w;
    const float cntf = (float)g_cnt[n];
#pragma unroll
    for (int nt = 0; nt < 8; nt++) {
        const int co = nt * 8 + 2 * q;
        const float bias0 = bA[co]     + cntf * bB[co];
        const float bias1 = bA[co + 1] + cntf * bB[co + 1];
#pragma unroll
        for (int mt = 0; mt < 2; mt++) {
            const int xa = mt * 16 + qid;
            const int xc = xa + 8;
            float r0 = acc[mt][nt][0] + bias0;   // (xa, co)
            float r1 = acc[mt][nt][1] + bias1;   // (xa, co+1)
            float r2 = acc[mt][nt][2] + bias0;   // (xc, co)
            float r3 = acc[mt][nt][3] + bias1;   // (xc, co+1)
            if (EPI == 0) {
                const int o0 = ((n * CCH + co) * HW + gy) * HW;
                r0 += resid[o0 + xa];
                r1 += resid[o0 + 1024 + xa];
                r2 += resid[o0 + xc];
                r3 += resid[o0 + 1024 + xc];
                out[o0 + xa]        = fmaxf(r0, 0.f);
                out[o0 + 1024 + xa] = fmaxf(r1, 0.f);
                out[o0 + xc]        = fmaxf(r2, 0.f);
                out[o0 + 1024 + xc] = fmaxf(r3, 0.f);
            } else {
                // paired store: co -> (cc=co>>3, slot=co&3, comp=(co>>2)&1)
                r0 = __uint_as_float(f2tf32(fmaxf(r0, 0.f)));
                r1 = __uint_as_float(f2tf32(fmaxf(r1, 0.f)));
                r2 = __uint_as_float(f2tf32(fmaxf(r2, 0.f)));
                r3 = __uint_as_float(f2tf32(fmaxf(r3, 0.f)));
                const int co1 = co + 1;
                const int b0 = ((((n * 8 + nt) * 4 + (co  & 3)) * 1024) + gy * 32) * 2 + ((co  >> 2) & 1);
                const int b1 = ((((n * 8 + nt) * 4 + (co1 & 3)) * 1024) + gy * 32) * 2 + ((co1 >> 2) & 1);
                out[b0 + 2 * xa] = r0;
                out[b1 + 2 * xa] = r1;
                out[b0 + 2 * xc] = r2;
                out[b1 + 2 * xc] = r3;
            }
        }
    }
}

// ---------------------------------------------------------------------------
extern "C" void kernel_launch(void* const* d_in, const int* in_sizes, int n_in,
                              void* d_out, int out_size) {
    const float* x    = (const float*)d_in[0];
    const float* w_x0 = (const float*)d_in[1];
    const float* b_x0 = (const float*)d_in[2];
    const float* w_n0 = (const float*)d_in[3];
    const float* b_n0 = (const float*)d_in[4];
    const float* w_x1 = (const float*)d_in[5];
    const float* b_x1 = (const float*)d_in[6];
    const float* w_n1 = (const float*)d_in[7];
    const float* b_n1 = (const float*)d_in[8];
    const void*  msk  = d_in[9];
    float* out = (float*)d_out;

    float2 *xp, *xs, *h, *hs;
    uint2* wprep;
    cudaGetSymbolAddress((void**)&xp, g_xp);
    cudaGetSymbolAddress((void**)&xs, g_xs);
    cudaGetSymbolAddress((void**)&h,  g_h);
    cudaGetSymbolAddress((void**)&hs, g_hs);
    cudaGetSymbolAddress((void**)&wprep, g_wprep);

    static bool attr_set = false;
    if (!attr_set) {
        cudaFuncSetAttribute(conv_kernel<0>, cudaFuncAttributeMaxDynamicSharedMemorySize,
                             SMEM_BYTES);
        cudaFuncSetAttribute(conv_kernel<1>, cudaFuncAttributeMaxDynamicSharedMemorySize,
                             SMEM_BYTES);
        attr_set = true;
    }

    detect_kernel<<<1, 256>>>(msk);
    build_kernel<<<1, 256>>>(msk);
    prep_weights<<<(WPREP_TOTAL + 255) / 256, 256>>>(w_x0, w_n0, w_x1, w_n1);
    pairify_kernel<<<NIMG * IMGSZ / 2 / 256, 256>>>(x, xp);

    dim3 agrid(NODES, 16);
    dim3 cgrid(4, NIMG);

    // layer 1: xs = agg(xp); h = relu(conv) stored paired+rounded
    agg_kernel<<<agrid, 256>>>((const float*)xp, (float*)xs);
    conv_kernel<1><<<cgrid, 256, SMEM_BYTES>>>(xp, xs, wprep, b_x0, b_n0,
                                               nullptr, (float*)h);

    // layer 2: hs = agg(h); out = relu(conv + x) standard fp32
    agg_kernel<<<agrid, 256>>>((const float*)h, (float*)hs);
    conv_kernel<0><<<cgrid, 256, SMEM_BYTES>>>(h, hs, wprep + 16 * W_CHUNK, b_x1, b_n1,
                                               x, out);
}